// round 2
// baseline (speedup 1.0000x reference)
#include <cuda_runtime.h>

// out = x @ (2048 * Wv @ Wo) + (2048 * bv @ Wo + bo)
// (the reference's einsum 'bvhd,bhqk->bvhd' sums softmax scores over q,k -> L=2048,
//  so q/k/softmax collapse to a scalar factor)

#define BM 128
#define BN 128
#define BK 16
#define TM 8
#define TN 8

// Scratch (allocation-free rule: __device__ globals)
__device__ float g_weff[1024 * 1024];
__device__ float g_beff[1024];

// C[M,N] = alpha * A[M,K] @ B[K,N] (+ bias[N] if bias != nullptr)
// All of M, N multiples of 128; K multiple of 16. No bounds checks.
__global__ __launch_bounds__(256) void sgemm_kernel(
    const float* __restrict__ A, const float* __restrict__ B,
    const float* __restrict__ bias, float* __restrict__ C,
    int M, int N, int K, float alpha)
{
    __shared__ float As[BK][BM];  // A stored transposed: As[k][m]
    __shared__ float Bs[BK][BN];

    const int tid = threadIdx.x;
    const int tx = tid % 16;          // 0..15  -> 8 output cols each
    const int ty = tid / 16;          // 0..15  -> 8 output rows each
    const int bm = blockIdx.y * BM;
    const int bn = blockIdx.x * BN;

    // Load mapping (float4):
    // A tile: 128 rows x 16 cols = 512 float4 -> 2 per thread
    const int a_row = tid / 4;            // 0..63
    const int a_col = (tid % 4) * 4;      // 0,4,8,12
    // B tile: 16 rows x 128 cols = 512 float4 -> 2 per thread
    const int b_row = tid / 32;           // 0..7
    const int b_col = (tid % 32) * 4;     // 0..124

    float acc[TM][TN];
    #pragma unroll
    for (int i = 0; i < TM; i++)
        #pragma unroll
        for (int j = 0; j < TN; j++)
            acc[i][j] = 0.0f;

    for (int k0 = 0; k0 < K; k0 += BK) {
        #pragma unroll
        for (int r = 0; r < 2; r++) {
            const int row = a_row + r * 64;
            const float4 v = *reinterpret_cast<const float4*>(
                &A[(size_t)(bm + row) * K + k0 + a_col]);
            As[a_col + 0][row] = v.x;
            As[a_col + 1][row] = v.y;
            As[a_col + 2][row] = v.z;
            As[a_col + 3][row] = v.w;
        }
        #pragma unroll
        for (int r = 0; r < 2; r++) {
            const int row = b_row + r * 8;
            *reinterpret_cast<float4*>(&Bs[row][b_col]) =
                *reinterpret_cast<const float4*>(&B[(size_t)(k0 + row) * N + bn + b_col]);
        }
        __syncthreads();

        #pragma unroll
        for (int k = 0; k < BK; k++) {
            float ra[TM], rb[TN];
            #pragma unroll
            for (int i = 0; i < TM; i += 4) {
                const float4 v = *reinterpret_cast<const float4*>(&As[k][ty * TM + i]);
                ra[i + 0] = v.x; ra[i + 1] = v.y; ra[i + 2] = v.z; ra[i + 3] = v.w;
            }
            #pragma unroll
            for (int j = 0; j < TN; j += 4) {
                const float4 v = *reinterpret_cast<const float4*>(&Bs[k][tx * TN + j]);
                rb[j + 0] = v.x; rb[j + 1] = v.y; rb[j + 2] = v.z; rb[j + 3] = v.w;
            }
            #pragma unroll
            for (int i = 0; i < TM; i++)
                #pragma unroll
                for (int j = 0; j < TN; j++)
                    acc[i][j] += ra[i] * rb[j];
        }
        __syncthreads();
    }

    #pragma unroll
    for (int i = 0; i < TM; i++) {
        const int row = bm + ty * TM + i;
        #pragma unroll
        for (int j = 0; j < TN; j += 4) {
            const int col = bn + tx * TN + j;
            float4 v;
            v.x = alpha * acc[i][j + 0];
            v.y = alpha * acc[i][j + 1];
            v.z = alpha * acc[i][j + 2];
            v.w = alpha * acc[i][j + 3];
            if (bias != nullptr) {
                const float4 b = *reinterpret_cast<const float4*>(&bias[col]);
                v.x += b.x; v.y += b.y; v.z += b.z; v.w += b.w;
            }
            *reinterpret_cast<float4*>(&C[(size_t)row * N + col]) = v;
        }
    }
}

// beff[j] = alpha * sum_k bv[k] * Wo[k*N + j] + bo[j]
// grid: N/128 blocks, 128 threads; thread owns one j, coalesced Wo reads.
__global__ void beff_kernel(const float* __restrict__ bv,
                            const float* __restrict__ Wo,
                            const float* __restrict__ bo,
                            float* __restrict__ beff,
                            int K, int N, float alpha)
{
    const int j = blockIdx.x * blockDim.x + threadIdx.x;
    if (j >= N) return;
    float s = 0.0f;
    #pragma unroll 4
    for (int k = 0; k < K; k++)
        s += bv[k] * Wo[(size_t)k * N + j];
    beff[j] = alpha * s + bo[j];
}

extern "C" void kernel_launch(void* const* d_in, const int* in_sizes, int n_in,
                              void* d_out, int out_size)
{
    // metadata order: x, encoder_x, Wq, bq, Wk, bk, Wv, bv, Wo, bo
    const float* x  = (const float*)d_in[0];
    const float* Wv = (const float*)d_in[6];
    const float* bv = (const float*)d_in[7];
    const float* Wo = (const float*)d_in[8];
    const float* bo = (const float*)d_in[9];
    float* out = (float*)d_out;

    const int Bsz = 4, L = 2048, D = 1024;   // QKV*H == D == 1024
    const int M = Bsz * L;                   // 8192
    const int N = D;                         // 1024
    const int K = D;                         // 1024
    const float scale = (float)L;            // 2048: sum of softmax over q,k

    float* weff = nullptr;
    float* beff = nullptr;
    cudaGetSymbolAddress((void**)&weff, g_weff);
    cudaGetSymbolAddress((void**)&beff, g_beff);

    // b_eff = 2048 * bv @ Wo + bo
    beff_kernel<<<N / 128, 128>>>(bv, Wo, bo, beff, K, N, scale);

    // W_eff = 2048 * Wv @ Wo   (1024 x 1024 x 1024)
    {
        dim3 grid(N / BN, K / BM);  // K rows of Wv = 1024
        sgemm_kernel<<<grid, 256>>>(Wv, Wo, nullptr, weff, K, N, K, scale);
    }

    // out = x @ W_eff + b_eff   (8192 x 1024 x 1024)
    {
        dim3 grid(N / BN, M / BM);
        sgemm_kernel<<<grid, 256>>>(x, weff, beff, out, M, N, K, 1.0f);
    }
}

// round 6
// speedup vs baseline: 2.2429x; 2.2429x over previous
#include <cuda_runtime.h>
#include <cuda_bf16.h>
#include <cstdint>
#include <cstddef>

// out = x @ (2048 * Wv @ Wo) + (2048 * bv @ Wo + bo)
// (reference's einsum 'bvhd,bhqk->bvhd' sums softmax over q,k -> factor L=2048)
// fp32 emulated as split-bf16: A@B ~= Ah@Bh + Al@Bh + Ah@Bl, fp32 accum,
// via mma.sync.m16n8k16 (arch-neutral PTX; tcgen05 unavailable: harness targets sm_103 non-'a').
//
// weffT[n][i] = sum_c Wo[c][n] * Wv[i][c]:  A = WoT (transposed), B = Wv (PLAIN).

// ---------------------------------------------------------------------------
__device__ __forceinline__ uint32_t smem_u32(const void* p) {
    uint32_t a;
    asm("{ .reg .u64 t; cvta.to.shared.u64 t, %1; cvt.u32.u64 %0, t; }" : "=r"(a) : "l"(p));
    return a;
}
__device__ __forceinline__ void cp_async16(uint32_t saddr, const void* gaddr) {
    asm volatile("cp.async.cg.shared.global [%0], [%1], 16;" :: "r"(saddr), "l"(gaddr));
}
#define CP_COMMIT() asm volatile("cp.async.commit_group;" ::: "memory")
template <int N> __device__ __forceinline__ void cp_wait() {
    asm volatile("cp.async.wait_group %0;" :: "n"(N) : "memory");
}
__device__ __forceinline__ void ldsm_x4(uint32_t* r, uint32_t addr) {
    asm volatile("ldmatrix.sync.aligned.m8n8.x4.shared.b16 {%0,%1,%2,%3}, [%4];"
        : "=r"(r[0]), "=r"(r[1]), "=r"(r[2]), "=r"(r[3]) : "r"(addr));
}
__device__ __forceinline__ void mma16816(float* c, const uint32_t* a, const uint32_t* b) {
    asm volatile(
        "mma.sync.aligned.m16n8k16.row.col.f32.bf16.bf16.f32 "
        "{%0,%1,%2,%3}, {%4,%5,%6,%7}, {%8,%9}, {%0,%1,%2,%3};"
        : "+f"(c[0]), "+f"(c[1]), "+f"(c[2]), "+f"(c[3])
        : "r"(a[0]), "r"(a[1]), "r"(a[2]), "r"(a[3]), "r"(b[0]), "r"(b[1]));
}

// ---------------------------------------------------------------------------
// Scratch (__device__ globals; no allocation allowed)
// ---------------------------------------------------------------------------
__device__ __nv_bfloat16 g_x_hi[8192 * 1024];
__device__ __nv_bfloat16 g_x_lo[8192 * 1024];
__device__ __nv_bfloat16 g_wv_hi[1024 * 1024];
__device__ __nv_bfloat16 g_wv_lo[1024 * 1024];
__device__ __nv_bfloat16 g_woT_hi[1024 * 1024];
__device__ __nv_bfloat16 g_woT_lo[1024 * 1024];
__device__ __nv_bfloat16 g_wT_hi[1024 * 1024];
__device__ __nv_bfloat16 g_wT_lo[1024 * 1024];
__device__ float g_beff[1024];

// ---------------------------------------------------------------------------
// Conversion kernels
// ---------------------------------------------------------------------------
__global__ void split_kernel(const float* __restrict__ in,
                             __nv_bfloat16* __restrict__ hi,
                             __nv_bfloat16* __restrict__ lo, int n4) {
    int i = blockIdx.x * blockDim.x + threadIdx.x;
    if (i >= n4) return;
    float4 v = reinterpret_cast<const float4*>(in)[i];
    __nv_bfloat16 h0 = __float2bfloat16(v.x), h1 = __float2bfloat16(v.y);
    __nv_bfloat16 h2 = __float2bfloat16(v.z), h3 = __float2bfloat16(v.w);
    __nv_bfloat162* hp = reinterpret_cast<__nv_bfloat162*>(hi);
    __nv_bfloat162* lp = reinterpret_cast<__nv_bfloat162*>(lo);
    hp[2 * i]     = __nv_bfloat162(h0, h1);
    hp[2 * i + 1] = __nv_bfloat162(h2, h3);
    lp[2 * i]     = __nv_bfloat162(__float2bfloat16(v.x - __bfloat162float(h0)),
                                   __float2bfloat16(v.y - __bfloat162float(h1)));
    lp[2 * i + 1] = __nv_bfloat162(__float2bfloat16(v.z - __bfloat162float(h2)),
                                   __float2bfloat16(v.w - __bfloat162float(h3)));
}

// Transposing split: out[n][c] = split(in[c][n]); 1024x1024
__global__ void splitT_kernel(const float* __restrict__ in,
                              __nv_bfloat16* __restrict__ hiT,
                              __nv_bfloat16* __restrict__ loT) {
    __shared__ float t[32][33];
    const int bx = blockIdx.x * 32, by = blockIdx.y * 32;
    const int tx = threadIdx.x, ty = threadIdx.y;  // 32 x 8
    #pragma unroll
    for (int i = 0; i < 32; i += 8)
        t[ty + i][tx] = in[(size_t)(by + ty + i) * 1024 + bx + tx];
    __syncthreads();
    #pragma unroll
    for (int i = 0; i < 32; i += 8) {
        float v = t[tx][ty + i];
        __nv_bfloat16 h = __float2bfloat16(v);
        size_t o = (size_t)(bx + ty + i) * 1024 + by + tx;
        hiT[o] = h;
        loT[o] = __float2bfloat16(v - __bfloat162float(h));
    }
}

// beff[j] = 2048 * sum_k bv[k]*Wo[k][j] + bo[j]; one block per j
__global__ void beff_kernel(const float* __restrict__ bv, const float* __restrict__ Wo,
                            const float* __restrict__ bo, float* __restrict__ beff) {
    __shared__ float red[256];
    const int j = blockIdx.x;
    float s = 0.0f;
    for (int k = threadIdx.x; k < 1024; k += 256)
        s += bv[k] * Wo[(size_t)k * 1024 + j];
    red[threadIdx.x] = s;
    __syncthreads();
    for (int st = 128; st > 0; st >>= 1) {
        if (threadIdx.x < st) red[threadIdx.x] += red[threadIdx.x + st];
        __syncthreads();
    }
    if (threadIdx.x == 0) beff[j] = 2048.0f * red[0] + bo[j];
}

// ---------------------------------------------------------------------------
// Split-bf16 GEMM via mma.sync: D[m][n] = sum_k A[m][k]*B[n][k]
//   A: [M x 1024] K-major (hi/lo), B: [N x 1024] K-major (hi/lo)
// MODE 0: out_f = D + bias;  MODE 1: (out_hi,out_lo) = split(D * scale)
// CTA tile 128x128, BK=32, 256 thr (8 warps, 2x4), warp tile 64x32,
// double-buffered cp.async, 80B-pitch smem (ldmatrix conflict-free).
// ---------------------------------------------------------------------------
#define PITCH 80
#define TILE_B (128 * PITCH)       // 10240 bytes: one 128x32 bf16 tile
#define STAGE_B (4 * TILE_B)       // AH, AL, BH, BL
#define SMEM_B (2 * STAGE_B)       // 81920

__device__ __forceinline__ void load_tile(uint32_t s, const __nv_bfloat16* g,
                                          int row0, int k0, int tid) {
    #pragma unroll
    for (int i = 0; i < 2; i++) {
        int idx = tid + i * 256;
        int r = idx >> 2, c = idx & 3;
        cp_async16(s + r * PITCH + c * 16,
                   g + (size_t)(row0 + r) * 1024 + k0 + c * 8);
    }
}

template <int MODE>
__global__ void __launch_bounds__(256, 1) mma_gemm(
    const __nv_bfloat16* __restrict__ A_hi, const __nv_bfloat16* __restrict__ A_lo,
    const __nv_bfloat16* __restrict__ B_hi, const __nv_bfloat16* __restrict__ B_lo,
    const float* __restrict__ bias, float* __restrict__ out_f,
    __nv_bfloat16* __restrict__ out_hi, __nv_bfloat16* __restrict__ out_lo,
    int K, float scale) {
    extern __shared__ char smem[];
    const uint32_t sb = smem_u32(smem);
    const int tid = threadIdx.x;
    const int lid = tid & 31;
    const int wid = tid >> 5;
    const int wm = wid >> 2;       // 0..1 -> 64 rows
    const int wn = wid & 3;        // 0..3 -> 32 cols
    const int bm = blockIdx.y * 128;
    const int bn = blockIdx.x * 128;

    float acc[4][4][4];
    #pragma unroll
    for (int mt = 0; mt < 4; mt++)
        #pragma unroll
        for (int nt = 0; nt < 4; nt++)
            #pragma unroll
            for (int e = 0; e < 4; e++) acc[mt][nt][e] = 0.0f;

    const int NC = K >> 5;  // BK=32 chunks

    // prologue: stage 0
    load_tile(sb + 0 * TILE_B, A_hi, bm, 0, tid);
    load_tile(sb + 1 * TILE_B, A_lo, bm, 0, tid);
    load_tile(sb + 2 * TILE_B, B_hi, bn, 0, tid);
    load_tile(sb + 3 * TILE_B, B_lo, bn, 0, tid);
    CP_COMMIT();

    // ldmatrix lane addressing (precomputed)
    const int a_r = lid & 15, a_h = lid >> 4;             // A: rows 0-15, k-half
    const int b_g = lid >> 3, b_r = lid & 7;              // B: group, row
    const int b_nt_add = b_g >> 1, b_kh = b_g & 1;

    for (int c = 0; c < NC; c++) {
        if (c + 1 < NC) {
            const uint32_t st = sb + ((c + 1) & 1) * STAGE_B;
            const int k0 = (c + 1) << 5;
            load_tile(st + 0 * TILE_B, A_hi, bm, k0, tid);
            load_tile(st + 1 * TILE_B, A_lo, bm, k0, tid);
            load_tile(st + 2 * TILE_B, B_hi, bn, k0, tid);
            load_tile(st + 3 * TILE_B, B_lo, bn, k0, tid);
            CP_COMMIT();
            cp_wait<1>();
        } else {
            cp_wait<0>();
        }
        __syncthreads();

        const uint32_t st = sb + (c & 1) * STAGE_B;
        #pragma unroll
        for (int ks = 0; ks < 2; ks++) {
            uint32_t ah[4][4], al[4][4], bh[4][2], bl[4][2];
            #pragma unroll
            for (int mt = 0; mt < 4; mt++) {
                uint32_t ad = st + (uint32_t)((wm * 64 + mt * 16 + a_r) * PITCH
                                              + (ks * 2 + a_h) * 16);
                ldsm_x4(ah[mt], ad);                 // AH tile
                ldsm_x4(al[mt], ad + TILE_B);        // AL tile
            }
            #pragma unroll
            for (int nt = 0; nt < 4; nt += 2) {
                uint32_t bd = st + 2 * TILE_B
                    + (uint32_t)((wn * 32 + (nt + b_nt_add) * 8 + b_r) * PITCH
                                 + (ks * 2 + b_kh) * 16);
                uint32_t t0[4], t1[4];
                ldsm_x4(t0, bd);                     // BH
                ldsm_x4(t1, bd + TILE_B);            // BL
                bh[nt][0] = t0[0]; bh[nt][1] = t0[1];
                bh[nt + 1][0] = t0[2]; bh[nt + 1][1] = t0[3];
                bl[nt][0] = t1[0]; bl[nt][1] = t1[1];
                bl[nt + 1][0] = t1[2]; bl[nt + 1][1] = t1[3];
            }
            #pragma unroll
            for (int mt = 0; mt < 4; mt++)
                #pragma unroll
                for (int nt = 0; nt < 4; nt++) {
                    mma16816(acc[mt][nt], ah[mt], bh[nt]);
                    mma16816(acc[mt][nt], al[mt], bh[nt]);
                    mma16816(acc[mt][nt], ah[mt], bl[nt]);
                }
        }
        __syncthreads();
    }

    // Epilogue: c0,c1 -> (row, col..col+1); c2,c3 -> (row+8, same cols)
    const int er = lid >> 2;           // 0..7
    const int ec = (lid & 3) * 2;      // 0,2,4,6
    #pragma unroll
    for (int mt = 0; mt < 4; mt++) {
        #pragma unroll
        for (int nt = 0; nt < 4; nt++) {
            const int row = bm + wm * 64 + mt * 16 + er;
            const int col = bn + wn * 32 + nt * 8 + ec;
            if (MODE == 0) {
                const float b0 = bias[col], b1 = bias[col + 1];
                float2 v0 = make_float2(acc[mt][nt][0] + b0, acc[mt][nt][1] + b1);
                float2 v1 = make_float2(acc[mt][nt][2] + b0, acc[mt][nt][3] + b1);
                *reinterpret_cast<float2*>(&out_f[(size_t)row * 1024 + col]) = v0;
                *reinterpret_cast<float2*>(&out_f[(size_t)(row + 8) * 1024 + col]) = v1;
            } else {
                #pragma unroll
                for (int half = 0; half < 2; half++) {
                    const float s0 = acc[mt][nt][2 * half + 0] * scale;
                    const float s1 = acc[mt][nt][2 * half + 1] * scale;
                    const __nv_bfloat16 h0 = __float2bfloat16(s0);
                    const __nv_bfloat16 h1 = __float2bfloat16(s1);
                    const size_t o = (size_t)(row + 8 * half) * 1024 + col;
                    *reinterpret_cast<__nv_bfloat162*>(&out_hi[o]) = __nv_bfloat162(h0, h1);
                    *reinterpret_cast<__nv_bfloat162*>(&out_lo[o]) = __nv_bfloat162(
                        __float2bfloat16(s0 - __bfloat162float(h0)),
                        __float2bfloat16(s1 - __bfloat162float(h1)));
                }
            }
        }
    }
}

// ---------------------------------------------------------------------------
extern "C" void kernel_launch(void* const* d_in, const int* in_sizes, int n_in,
                              void* d_out, int out_size) {
    const float* x  = (const float*)d_in[0];
    const float* Wv = (const float*)d_in[6];
    const float* bv = (const float*)d_in[7];
    const float* Wo = (const float*)d_in[8];
    const float* bo = (const float*)d_in[9];
    float* out = (float*)d_out;

    __nv_bfloat16 *x_hi, *x_lo, *wv_hi, *wv_lo, *woT_hi, *woT_lo, *wT_hi, *wT_lo;
    float* beff;
    cudaGetSymbolAddress((void**)&x_hi, g_x_hi);
    cudaGetSymbolAddress((void**)&x_lo, g_x_lo);
    cudaGetSymbolAddress((void**)&wv_hi, g_wv_hi);
    cudaGetSymbolAddress((void**)&wv_lo, g_wv_lo);
    cudaGetSymbolAddress((void**)&woT_hi, g_woT_hi);
    cudaGetSymbolAddress((void**)&woT_lo, g_woT_lo);
    cudaGetSymbolAddress((void**)&wT_hi, g_wT_hi);
    cudaGetSymbolAddress((void**)&wT_lo, g_wT_lo);
    cudaGetSymbolAddress((void**)&beff, g_beff);

    cudaFuncSetAttribute(mma_gemm<0>, cudaFuncAttributeMaxDynamicSharedMemorySize, SMEM_B);
    cudaFuncSetAttribute(mma_gemm<1>, cudaFuncAttributeMaxDynamicSharedMemorySize, SMEM_B);

    // splits: x and Wv plain (row index = their leading dim); Wo transposed.
    // weffT[n][i] = sum_c WoT[n][c] * Wv[i][c]  ->  A = WoT, B = Wv (plain!)
    split_kernel<<<8192, 256>>>(x, x_hi, x_lo, 8192 * 1024 / 4);
    split_kernel<<<1024, 256>>>(Wv, wv_hi, wv_lo, 1024 * 1024 / 4);
    splitT_kernel<<<dim3(32, 32), dim3(32, 8)>>>(Wo, woT_hi, woT_lo);
    beff_kernel<<<1024, 256>>>(bv, Wo, bo, beff);

    // weffT[n][i] = 2048 * sum_c WoT[n][c] * Wv[i][c]   (epilogue re-splits)
    mma_gemm<1><<<dim3(8, 8), 256, SMEM_B>>>(
        woT_hi, woT_lo, wv_hi, wv_lo, nullptr, nullptr, wT_hi, wT_lo, 1024, 2048.0f);

    // out[m][n] = sum_i x[m][i] * weffT[n][i] + beff[n]
    mma_gemm<0><<<dim3(8, 64), 256, SMEM_B>>>(
        x_hi, x_lo, wT_hi, wT_lo, beff, out, nullptr, nullptr, 1024, 1.0f);
}